// round 16
// baseline (speedup 1.0000x reference)
#include <cuda_runtime.h>
#include <cuda_fp16.h>
#include <stdint.h>

// ---------------- problem constants ----------------
#define NE    8
#define DIN   2048
#define DOUT  2048
#define NTOK  8192
#define NPAIR (NTOK * 2)
#define WBLKS (NE * DOUT * DIN / (256 * 8))   // 16384 convert-W blocks

// ---------------- GEMM tiling (R3-proven core) ----------------
#define BM     128
#define BN     128
#define BK     64
#define ASTR   72
#define KSTEPS (DIN / BK)          // 32
#define NTILE  (DOUT / BN)         // 16
#define MAXT   136
#define NPERS  296                 // persistent CTAs: 2 per SM x 148

#define A_STG_B (BM * ASTR * 2)
#define B_STG_B (BN * ASTR * 2)
#define STG_B   (A_STG_B + B_STG_B)
#define SMEM_WT (2 * STG_B)
#define SMEM_TOK (SMEM_WT + BM * 4)
#define SMEM_CTL (SMEM_TOK + BM * 4)
#define SMEM_TOT (SMEM_CTL + 16)              // 74768 -> 2 CTAs/SM

// ---------------- device scratch ----------------
__device__ __align__(16) __half g_xh[NTOK * DIN];        // fp16 activations, TOKEN order
__device__ __align__(16) __half g_wh[NE * DOUT * DIN];   // fp16 weights

__device__ int   g_cnt[NE];
__device__ int   g_pos[NE];
__device__ int   g_off[NE + 1];
__device__ int   g_tok[NPAIR];
__device__ float g_wt[NPAIR];
__device__ int   g_topi[NPAIR];
__device__ float g_topp[NPAIR];
__device__ int   g_tile_e[MAXT];
__device__ int   g_tile_r0[MAXT];
__device__ int   g_tile_rows[MAXT];
__device__ int   g_ntiles;
__device__ int   g_done;
__device__ int   g_tile_ctr;        // persistent-gemm work counter

// ---------------- helpers ----------------
__device__ __forceinline__ void cpa16(uint32_t dst, const void* src) {
    asm volatile("cp.async.cg.shared.global [%0], [%1], 16;\n" :: "r"(dst), "l"(src));
}
__device__ __forceinline__ void ldsm_x4(uint32_t* r, uint32_t addr) {
    asm volatile("ldmatrix.sync.aligned.m8n8.x4.shared.b16 {%0,%1,%2,%3}, [%4];"
                 : "=r"(r[0]), "=r"(r[1]), "=r"(r[2]), "=r"(r[3]) : "r"(addr));
}
__device__ __forceinline__ void mma16816(float* c, const uint32_t* a, const uint32_t* b) {
    asm volatile(
        "mma.sync.aligned.m16n8k16.row.col.f32.f16.f16.f32 "
        "{%0,%1,%2,%3}, {%4,%5,%6,%7}, {%8,%9}, {%0,%1,%2,%3};\n"
        : "+f"(c[0]), "+f"(c[1]), "+f"(c[2]), "+f"(c[3])
        : "r"(a[0]), "r"(a[1]), "r"(a[2]), "r"(a[3]), "r"(b[0]), "r"(b[1]));
}
__device__ __forceinline__ void red2(float* addr, float v0, float v1) {
    asm volatile("red.global.add.v2.f32 [%0], {%1, %2};"
                 :: "l"(addr), "f"(v0), "f"(v1) : "memory");
}
__device__ __forceinline__ uint32_t pack2h(float a, float b) {
    __half2 h = __floats2half2_rn(a, b);
    return *(uint32_t*)&h;
}

// ---------------- launch 0: prep (gate + x convert + out zero + scan | W convert) ----------------
__global__ void prep_kernel(const float* __restrict__ x,
                            const float* __restrict__ gw,
                            const float* __restrict__ gb,
                            const float* __restrict__ ew,
                            float* __restrict__ out) {
    int bid = blockIdx.x;

    if (bid >= NTOK) {
        size_t idx = (size_t)(bid - NTOK) * 256 + threadIdx.x;
        const float4* ws = (const float4*)ew;
        float4 a = ws[idx * 2], b = ws[idx * 2 + 1];
        uint4 o;
        o.x = pack2h(a.x, a.y);  o.y = pack2h(a.z, a.w);
        o.z = pack2h(b.x, b.y);  o.w = pack2h(b.z, b.w);
        ((uint4*)g_wh)[idx] = o;
        return;
    }

    int t = bid;
    int i = threadIdx.x;
    const float4* xs = (const float4*)(x + (size_t)t * DIN);
    float4 a = xs[i * 2], b = xs[i * 2 + 1];

    {
        uint4 o;
        o.x = pack2h(a.x, a.y);  o.y = pack2h(a.z, a.w);
        o.z = pack2h(b.x, b.y);  o.w = pack2h(b.z, b.w);
        ((uint4*)(g_xh + (size_t)t * DIN))[i] = o;
        float4 z = make_float4(0.f, 0.f, 0.f, 0.f);
        float4* o4 = (float4*)(out + (size_t)t * DOUT);
        o4[i * 2]     = z;
        o4[i * 2 + 1] = z;
    }

    float acc[NE];
#pragma unroll
    for (int e = 0; e < NE; e++) {
        const float4* gwe = (const float4*)(gw + (size_t)e * DIN + i * 8);
        float4 w0 = gwe[0], w1 = gwe[1];
        acc[e] = a.x * w0.x + a.y * w0.y + a.z * w0.z + a.w * w0.w
               + b.x * w1.x + b.y * w1.y + b.z * w1.z + b.w * w1.w;
    }
#pragma unroll
    for (int off = 16; off > 0; off >>= 1)
#pragma unroll
        for (int e = 0; e < NE; e++)
            acc[e] += __shfl_xor_sync(0xffffffffu, acc[e], off);

    __shared__ float red[NE][8];
    int warp = threadIdx.x >> 5, lane = threadIdx.x & 31;
    if (lane == 0)
#pragma unroll
        for (int e = 0; e < NE; e++) red[e][warp] = acc[e];
    __syncthreads();

    if (threadIdx.x == 0) {
        float lg[NE];
#pragma unroll
        for (int e = 0; e < NE; e++) {
            float s = 0.f;
#pragma unroll
            for (int w = 0; w < 8; w++) s += red[e][w];
            lg[e] = s + gb[e];
        }
        float m = lg[0];
#pragma unroll
        for (int e = 1; e < NE; e++) m = fmaxf(m, lg[e]);
        float pz[NE], Z = 0.f;
#pragma unroll
        for (int e = 0; e < NE; e++) { pz[e] = expf(lg[e] - m); Z += pz[e]; }
        int i1 = -1, i2 = -1; float m1 = -1.f, m2 = -1.f;
#pragma unroll
        for (int e = 0; e < NE; e++) {
            float p = pz[e];
            if (p > m1)      { m2 = m1; i2 = i1; m1 = p; i1 = e; }
            else if (p > m2) { m2 = p; i2 = e; }
        }
        float inv = 1.f / Z;
        g_topi[t * 2]     = i1;  g_topp[t * 2]     = m1 * inv;
        g_topi[t * 2 + 1] = i2;  g_topp[t * 2 + 1] = m2 * inv;
        atomicAdd(&g_cnt[i1], 1);
        atomicAdd(&g_cnt[i2], 1);

        __threadfence();
        int old = atomicAdd(&g_done, 1);
        if (old == NTOK - 1) {
            int off = 0, nt = 0;
            for (int e = 0; e < NE; e++) {
                g_off[e] = off;
                int c = g_cnt[e];
                g_cnt[e] = 0;
                for (int r = 0; r < c; r += BM) {
                    g_tile_e[nt] = e;
                    g_tile_r0[nt] = off + r;
                    g_tile_rows[nt] = (c - r < BM) ? (c - r) : BM;
                    nt++;
                }
                off += c;
            }
            g_off[NE] = off;
            g_ntiles = nt;
            g_done = 0;
            __threadfence();
        }
    }
}

// ---------------- launch 1: scatter ----------------
__global__ void scatter_kernel() {
    int t = blockIdx.x * blockDim.x + threadIdx.x;
    if (t >= NTOK) return;
#pragma unroll
    for (int k = 0; k < 2; k++) {
        int e = g_topi[t * 2 + k];
        float p = g_topp[t * 2 + k];
        int pos = atomicAdd(&g_pos[e], 1);
        int slot = g_off[e] + pos;
        g_tok[slot] = t;
        g_wt[slot]  = p;
    }
}

// ---------------- launch 2: reset g_pos + tile counter ----------------
__global__ void reset_pos_kernel() {
    if (threadIdx.x < NE) g_pos[threadIdx.x] = 0;
    if (threadIdx.x == 0) g_tile_ctr = 0;
}

// ---------------- launch 3: persistent grouped GEMM (work-stealing) ----------------
extern __shared__ char dsm[];

__global__ __launch_bounds__(256, 2) void gemm_kernel(const float* __restrict__ bias,
                                                      float* __restrict__ out) {
    float* wt_s  = (float*)(dsm + SMEM_WT);
    int*   tok_s = (int*)(dsm + SMEM_TOK);
    int*   ctl_s = (int*)(dsm + SMEM_CTL);

    int tid = threadIdx.x;
    int wid = tid >> 5, lane = tid & 31;
    int wm = wid >> 2, wn = wid & 3;
    int a_r = lane & 15, a_k = (lane >> 4) * 8;
    int b_r = ((lane >> 4) * 8) + (lane & 7), b_k = ((lane >> 3) & 1) * 8;
    int g = lane >> 2, tg = lane & 3;

    int lrow = tid >> 1;
    int lch  = (tid & 1) * 4;

    uint32_t aS[2], bS[2];
    uint32_t aL[2][4], bL[2][2];
#pragma unroll
    for (int s = 0; s < 2; s++) {
        char* Ab = dsm + s * STG_B;
        char* Bb = dsm + s * STG_B + A_STG_B;
        aS[s] = (uint32_t)__cvta_generic_to_shared(Ab) + (lrow * ASTR + lch * 8) * 2;
        bS[s] = (uint32_t)__cvta_generic_to_shared(Bb) + (lrow * ASTR + lch * 8) * 2;
#pragma unroll
        for (int im = 0; im < 4; im++)
            aL[s][im] = (uint32_t)__cvta_generic_to_shared(
                Ab + ((wm * 64 + im * 16 + a_r) * ASTR + a_k) * 2);
#pragma unroll
        for (int ip = 0; ip < 2; ip++)
            bL[s][ip] = (uint32_t)__cvta_generic_to_shared(
                Bb + ((wn * 32 + ip * 16 + b_r) * ASTR + b_k) * 2);
    }

    while (true) {
        // ---- steal a tile ----
        if (tid == 0) ctl_s[0] = atomicAdd(&g_tile_ctr, 1);
        __syncthreads();
        int tile = ctl_s[0];
        int nwork = g_ntiles * NTILE;
        if (tile >= nwork) break;
        int mt = tile >> 4;                  // NTILE = 16
        int n0 = (tile & 15) * BN;
        int e    = g_tile_e[mt];
        int row0 = g_tile_r0[mt];
        int rows = g_tile_rows[mt];

        if (tid < BM) {
            tok_s[tid] = (tid < rows) ? g_tok[row0 + tid] : 0;
            wt_s[tid]  = (tid < rows) ? g_wt[row0 + tid] : 0.f;
        }
        __syncthreads();

        const __half* asrc = g_xh + (size_t)tok_s[lrow] * DIN + lch * 8;
        const __half* bsrc = g_wh + ((size_t)e * DOUT + n0 + lrow) * DIN + lch * 8;

        auto issue = [&](int step, int buf) {
            const __half* as = asrc + step * BK;
            const __half* bs = bsrc + step * BK;
#pragma unroll
            for (int i = 0; i < 4; i++) {
                cpa16(aS[buf] + i * 16, as + i * 8);
                cpa16(bS[buf] + i * 16, bs + i * 8);
            }
        };

        float acc[4][4][4];
#pragma unroll
        for (int im = 0; im < 4; im++)
#pragma unroll
            for (int in = 0; in < 4; in++)
#pragma unroll
                for (int j = 0; j < 4; j++) acc[im][in][j] = 0.f;

        issue(0, 0);
        asm volatile("cp.async.commit_group;\n");
        int cur = 0;
        for (int s = 0; s < KSTEPS; s++) {
            if (s + 1 < KSTEPS) issue(s + 1, cur ^ 1);
            asm volatile("cp.async.commit_group;\n");
            asm volatile("cp.async.wait_group 1;\n");
            __syncthreads();

#pragma unroll
            for (int kk = 0; kk < BK; kk += 16) {
                uint32_t a[4][4], b[4][2];
#pragma unroll
                for (int im = 0; im < 4; im++)
                    ldsm_x4(a[im], aL[cur][im] + kk * 2);
#pragma unroll
                for (int ip = 0; ip < 2; ip++) {
                    uint32_t r[4];
                    ldsm_x4(r, bL[cur][ip] + kk * 2);
                    b[2 * ip][0] = r[0];     b[2 * ip][1] = r[1];
                    b[2 * ip + 1][0] = r[2]; b[2 * ip + 1][1] = r[3];
                }
#pragma unroll
                for (int im = 0; im < 4; im++)
#pragma unroll
                    for (int in = 0; in < 4; in++)
                        mma16816(acc[im][in], a[im], b[in]);
            }
            __syncthreads();
            cur ^= 1;
        }

        // ---- epilogue: vector reductions into out ----
#pragma unroll
        for (int im = 0; im < 4; im++) {
            int r0 = wm * 64 + im * 16 + g;
#pragma unroll
            for (int half = 0; half < 2; half++) {
                int r = r0 + half * 8;
                if (r < rows) {
                    int t = tok_s[r];
                    float w = wt_s[r];
                    float* orow = out + (size_t)t * DOUT + n0;
                    const float* bp = bias + (size_t)e * DOUT + n0;
#pragma unroll
                    for (int in = 0; in < 4; in++) {
                        int c = wn * 32 + in * 8 + tg * 2;
                        red2(&orow[c],
                             w * (acc[im][in][2 * half]     + bp[c]),
                             w * (acc[im][in][2 * half + 1] + bp[c + 1]));
                    }
                }
            }
        }
        __syncthreads();   // protect tok_s/wt_s before next tile
    }
}

// ---------------- launch ----------------
extern "C" void kernel_launch(void* const* d_in, const int* in_sizes, int n_in,
                              void* d_out, int out_size) {
    const float* x  = (const float*)d_in[0];
    const float* ew = (const float*)d_in[1];
    const float* eb = (const float*)d_in[2];
    const float* gw = (const float*)d_in[3];
    const float* gb = (const float*)d_in[4];
    float* out = (float*)d_out;

    cudaFuncSetAttribute(gemm_kernel, cudaFuncAttributeMaxDynamicSharedMemorySize, SMEM_TOT);

    prep_kernel<<<NTOK + WBLKS, 256>>>(x, gw, gb, ew, out);
    scatter_kernel<<<(NTOK + 255) / 256, 256>>>();
    reset_pos_kernel<<<1, 32>>>();
    gemm_kernel<<<NPERS, 256, SMEM_TOT>>>(eb, out);   // profiled slot
}